// round 1
// baseline (speedup 1.0000x reference)
#include <cuda_runtime.h>

// y[b,o] = sum_j relu(w[o,j] * x_aug[b,j]),  x_aug = [x | 1]
//        = 0.5 * ( sum_{j<256} w*x + sum_{j<256} |w|*|x| ) + max(w[o,256], 0)
//
// B=8192, OUT=256, K=256 (+bias col). Two fused GEMMs into one accumulator.

#define BDIM   8192
#define KDIM   256
#define NDIM   256
#define WSTRIDE 257   // weight row stride (IN+1)

#define BM 128
#define BN 128
#define BK 16
#define PAD 132       // padded smem row (conflict reduction + 16B alignment)

__global__ __launch_bounds__(256, 1)
void skan_linear_kernel(const float* __restrict__ x,
                        const float* __restrict__ w,
                        float* __restrict__ out)
{
    __shared__ float As[2][BK][PAD];   // k-major x tile:  As[k][row]
    __shared__ float Bs[2][BK][PAD];   // k-major w tile:  Bs[k][col]

    const int tid = threadIdx.x;
    const int bm = blockIdx.y * BM;
    const int bn = blockIdx.x * BN;

    // compute-phase mapping: 16x16 threads, each owns 8x8 outputs
    const int tx = tid & 15;    // output-col group
    const int ty = tid >> 4;    // output-row group

    // x gmem->smem mapping: float4 along k, 2 rows per thread
    const int lr = tid >> 2;          // 0..63
    const int lk = (tid & 3) * 4;     // 0,4,8,12

    // w gmem->smem mapping: scalar along k (stride-257 rows break float4 alignment)
    const int wkk = tid & 15;         // k within tile
    const int wo  = tid >> 4;         // 0..15, col base (8 passes of +16)

    float acc[8][8];
#pragma unroll
    for (int i = 0; i < 8; i++)
#pragma unroll
        for (int j = 0; j < 8; j++) acc[i][j] = 0.0f;

    float4 xr0, xr1;
    float  wr[8];

    // ---- prologue: load k-tile 0 into smem buf 0 ----
    {
        const int k0 = 0;
        xr0 = *reinterpret_cast<const float4*>(x + (bm + lr)      * KDIM + k0 + lk);
        xr1 = *reinterpret_cast<const float4*>(x + (bm + lr + 64) * KDIM + k0 + lk);
#pragma unroll
        for (int p = 0; p < 8; p++)
            wr[p] = w[(bn + wo + 16 * p) * WSTRIDE + k0 + wkk];

        const float* xv0 = reinterpret_cast<const float*>(&xr0);
        const float* xv1 = reinterpret_cast<const float*>(&xr1);
#pragma unroll
        for (int i = 0; i < 4; i++) {
            As[0][lk + i][lr]      = xv0[i];
            As[0][lk + i][lr + 64] = xv1[i];
        }
#pragma unroll
        for (int p = 0; p < 8; p++)
            Bs[0][wkk][wo + 16 * p] = wr[p];
    }
    __syncthreads();

    int buf = 0;
    const int NKT = KDIM / BK;   // 16 k-tiles

    for (int kt = 0; kt < NKT; kt++) {
        // prefetch next tile into registers
        if (kt + 1 < NKT) {
            const int k0 = (kt + 1) * BK;
            xr0 = *reinterpret_cast<const float4*>(x + (bm + lr)      * KDIM + k0 + lk);
            xr1 = *reinterpret_cast<const float4*>(x + (bm + lr + 64) * KDIM + k0 + lk);
#pragma unroll
            for (int p = 0; p < 8; p++)
                wr[p] = w[(bn + wo + 16 * p) * WSTRIDE + k0 + wkk];
        }

        // compute on current buffer
#pragma unroll
        for (int kk = 0; kk < BK; kk++) {
            float a[8], b[8], aa[8], ab[8];
            const float* arow = &As[buf][kk][ty * 8];
            const float* brow = &Bs[buf][kk][tx * 8];
#pragma unroll
            for (int i = 0; i < 8; i++) { a[i] = arow[i]; aa[i] = fabsf(a[i]); }
#pragma unroll
            for (int j = 0; j < 8; j++) { b[j] = brow[j]; ab[j] = fabsf(b[j]); }
#pragma unroll
            for (int i = 0; i < 8; i++)
#pragma unroll
                for (int j = 0; j < 8; j++) {
                    acc[i][j] = fmaf(a[i],  b[j],  acc[i][j]);
                    acc[i][j] = fmaf(aa[i], ab[j], acc[i][j]);
                }
        }

        // store prefetched tile into other buffer
        if (kt + 1 < NKT) {
            const int nbuf = buf ^ 1;
            const float* xv0 = reinterpret_cast<const float*>(&xr0);
            const float* xv1 = reinterpret_cast<const float*>(&xr1);
#pragma unroll
            for (int i = 0; i < 4; i++) {
                As[nbuf][lk + i][lr]      = xv0[i];
                As[nbuf][lk + i][lr + 64] = xv1[i];
            }
#pragma unroll
            for (int p = 0; p < 8; p++)
                Bs[nbuf][wkk][wo + 16 * p] = wr[p];
            __syncthreads();
            buf = nbuf;
        }
    }

    // ---- epilogue: y = 0.5*acc + relu(bias col) ----
    float bias[8];
#pragma unroll
    for (int j = 0; j < 8; j++)
        bias[j] = fmaxf(w[(bn + tx * 8 + j) * WSTRIDE + 256], 0.0f);

#pragma unroll
    for (int i = 0; i < 8; i++) {
        const int row = bm + ty * 8 + i;
        float4 v0, v1;
        v0.x = 0.5f * acc[i][0] + bias[0];
        v0.y = 0.5f * acc[i][1] + bias[1];
        v0.z = 0.5f * acc[i][2] + bias[2];
        v0.w = 0.5f * acc[i][3] + bias[3];
        v1.x = 0.5f * acc[i][4] + bias[4];
        v1.y = 0.5f * acc[i][5] + bias[5];
        v1.z = 0.5f * acc[i][6] + bias[6];
        v1.w = 0.5f * acc[i][7] + bias[7];
        float* o = out + (size_t)row * NDIM + bn + tx * 8;
        *reinterpret_cast<float4*>(o)     = v0;
        *reinterpret_cast<float4*>(o + 4) = v1;
    }
}

extern "C" void kernel_launch(void* const* d_in, const int* in_sizes, int n_in,
                              void* d_out, int out_size)
{
    const float* x = (const float*)d_in[0];     // (8192, 256)
    const float* w = (const float*)d_in[1];     // (256, 257)
    float* out = (float*)d_out;                 // (8192, 256)

    dim3 grid(NDIM / BN, BDIM / BM);            // (2, 64) = 128 CTAs
    dim3 block(256);
    skan_linear_kernel<<<grid, block>>>(x, w, out);
}

// round 2
// speedup vs baseline: 1.1592x; 1.1592x over previous
#include <cuda_runtime.h>
#include <cstdint>

// y[b,o] = sum_j relu(w[o,j] * x_aug[b,j]),  x_aug = [x | 1]
//        = 0.5 * ( sum_{j<256} w*x + sum_{j<256} |w|*|x| ) + max(w[o,256], 0)
//
// Inner loops use packed fma.rn.f32x2 (FFMA2): 2 FMAs per fma-pipe slot.

#define BDIM   8192
#define KDIM   256
#define NDIM   256
#define WSTRIDE 257

#define BM 128
#define BN 128
#define BK 16
#define PAD 132

#define FMA2(acc, a, b) \
    asm("fma.rn.f32x2 %0, %1, %2, %0;" : "+l"(acc) : "l"(a), "l"(b))
#define PACK2(out, lo, hi) \
    asm("mov.b64 %0, {%1, %2};" : "=l"(out) : "f"(lo), "f"(hi))

__global__ __launch_bounds__(256, 1)
void skan_linear_kernel(const float* __restrict__ x,
                        const float* __restrict__ w,
                        float* __restrict__ out)
{
    __shared__ float As[2][BK][PAD];   // k-major x tile:  As[k][row]
    __shared__ float Bs[2][BK][PAD];   // k-major w tile:  Bs[k][col]

    const int tid = threadIdx.x;
    const int bm = blockIdx.y * BM;
    const int bn = blockIdx.x * BN;

    const int tx = tid & 15;    // output-col group (8 cols = 4 pairs)
    const int ty = tid >> 4;    // output-row group (8 rows)

    // x gmem->smem: float4 along k, 2 rows per thread
    const int lr = tid >> 2;
    const int lk = (tid & 3) * 4;

    // w gmem->smem: scalar along k
    const int wkk = tid & 15;
    const int wo  = tid >> 4;

    // packed accumulators: acc2[i][jp] = (y[i][2jp], y[i][2jp+1])
    unsigned long long acc2[8][4];
#pragma unroll
    for (int i = 0; i < 8; i++)
#pragma unroll
        for (int jp = 0; jp < 4; jp++) acc2[i][jp] = 0ULL;

    float4 xr0, xr1;
    float  wr[8];

    // ---- prologue: k-tile 0 -> buf 0 ----
    {
        xr0 = *reinterpret_cast<const float4*>(x + (bm + lr)      * KDIM + lk);
        xr1 = *reinterpret_cast<const float4*>(x + (bm + lr + 64) * KDIM + lk);
#pragma unroll
        for (int p = 0; p < 8; p++)
            wr[p] = w[(bn + wo + 16 * p) * WSTRIDE + wkk];

        const float* xv0 = reinterpret_cast<const float*>(&xr0);
        const float* xv1 = reinterpret_cast<const float*>(&xr1);
#pragma unroll
        for (int i = 0; i < 4; i++) {
            As[0][lk + i][lr]      = xv0[i];
            As[0][lk + i][lr + 64] = xv1[i];
        }
#pragma unroll
        for (int p = 0; p < 8; p++)
            Bs[0][wkk][wo + 16 * p] = wr[p];
    }
    __syncthreads();

    int buf = 0;
    const int NKT = KDIM / BK;

    for (int kt = 0; kt < NKT; kt++) {
        if (kt + 1 < NKT) {
            const int k0 = (kt + 1) * BK;
            xr0 = *reinterpret_cast<const float4*>(x + (bm + lr)      * KDIM + k0 + lk);
            xr1 = *reinterpret_cast<const float4*>(x + (bm + lr + 64) * KDIM + k0 + lk);
#pragma unroll
            for (int p = 0; p < 8; p++)
                wr[p] = w[(bn + wo + 16 * p) * WSTRIDE + k0 + wkk];
        }

#pragma unroll
        for (int kk = 0; kk < BK; kk++) {
            // a fragment: 8 floats
            const float4 af0 = *reinterpret_cast<const float4*>(&As[buf][kk][ty * 8]);
            const float4 af1 = *reinterpret_cast<const float4*>(&As[buf][kk][ty * 8 + 4]);
            float a[8] = {af0.x, af0.y, af0.z, af0.w, af1.x, af1.y, af1.z, af1.w};

            // b fragment: 8 floats loaded directly as 4 packed f32x2 pairs
            const ulonglong2 bp0 = *reinterpret_cast<const ulonglong2*>(&Bs[buf][kk][tx * 8]);
            const ulonglong2 bp1 = *reinterpret_cast<const ulonglong2*>(&Bs[buf][kk][tx * 8 + 4]);
            unsigned long long b2[4]  = {bp0.x, bp0.y, bp1.x, bp1.y};
            unsigned long long ab2[4];
#pragma unroll
            for (int jp = 0; jp < 4; jp++)
                ab2[jp] = b2[jp] & 0x7FFFFFFF7FFFFFFFULL;   // packed |b|

            unsigned long long a2[8], aa2[8];
#pragma unroll
            for (int i = 0; i < 8; i++) {
                PACK2(a2[i], a[i], a[i]);
                const float ai = fabsf(a[i]);
                PACK2(aa2[i], ai, ai);
            }

#pragma unroll
            for (int i = 0; i < 8; i++)
#pragma unroll
                for (int jp = 0; jp < 4; jp++) {
                    FMA2(acc2[i][jp], a2[i],  b2[jp]);
                    FMA2(acc2[i][jp], aa2[i], ab2[jp]);
                }
        }

        if (kt + 1 < NKT) {
            const int nbuf = buf ^ 1;
            const float* xv0 = reinterpret_cast<const float*>(&xr0);
            const float* xv1 = reinterpret_cast<const float*>(&xr1);
#pragma unroll
            for (int i = 0; i < 4; i++) {
                As[nbuf][lk + i][lr]      = xv0[i];
                As[nbuf][lk + i][lr + 64] = xv1[i];
            }
#pragma unroll
            for (int p = 0; p < 8; p++)
                Bs[nbuf][wkk][wo + 16 * p] = wr[p];
            __syncthreads();
            buf = nbuf;
        }
    }

    // ---- epilogue: y = 0.5*acc + relu(bias col) ----
    float bias[8];
#pragma unroll
    for (int j = 0; j < 8; j++)
        bias[j] = fmaxf(w[(bn + tx * 8 + j) * WSTRIDE + 256], 0.0f);

#pragma unroll
    for (int i = 0; i < 8; i++) {
        const int row = bm + ty * 8 + i;
        float acc[8];
#pragma unroll
        for (int jp = 0; jp < 4; jp++) {
            unsigned int lo, hi;
            asm("mov.b64 {%0, %1}, %2;" : "=r"(lo), "=r"(hi) : "l"(acc2[i][jp]));
            acc[2 * jp]     = __uint_as_float(lo);
            acc[2 * jp + 1] = __uint_as_float(hi);
        }
        float4 v0, v1;
        v0.x = 0.5f * acc[0] + bias[0];
        v0.y = 0.5f * acc[1] + bias[1];
        v0.z = 0.5f * acc[2] + bias[2];
        v0.w = 0.5f * acc[3] + bias[3];
        v1.x = 0.5f * acc[4] + bias[4];
        v1.y = 0.5f * acc[5] + bias[5];
        v1.z = 0.5f * acc[6] + bias[6];
        v1.w = 0.5f * acc[7] + bias[7];
        float* o = out + (size_t)row * NDIM + bn + tx * 8;
        *reinterpret_cast<float4*>(o)     = v0;
        *reinterpret_cast<float4*>(o + 4) = v1;
    }
}

extern "C" void kernel_launch(void* const* d_in, const int* in_sizes, int n_in,
                              void* d_out, int out_size)
{
    const float* x = (const float*)d_in[0];     // (8192, 256)
    const float* w = (const float*)d_in[1];     // (256, 257)
    float* out = (float*)d_out;                 // (8192, 256)

    dim3 grid(NDIM / BN, BDIM / BM);            // (2, 64) = 128 CTAs
    dim3 block(256);
    skan_linear_kernel<<<grid, block>>>(x, w, out);
}

// round 5
// speedup vs baseline: 3.5853x; 3.0929x over previous
#include <cuda_runtime.h>
#include <cuda_fp16.h>
#include <cstdint>

// y[b,o] = sum_j relu(w[o,j]*x_aug[b,j])
//        = 0.5*( x.w + |x|.|w| ) + relu(w[o,256])
// fp16 mma.sync m16n8k16, abs computed on packed fp16x2 registers,
// both terms accumulated into the same fp32 C fragments.
// B loaded with NON-trans ldmatrix (smem [n][k], k contiguous => B-operand
// pairs {k,k+1}@fixed n are contiguous smem halves).

#define BM 128
#define BN 128
#define KDIM 256
#define WSTRIDE 257
#define NDIM 256

#define TILE_BYTES 16384          // 128 rows x 64 fp16 (128B rows)
#define B_OFF (2 * TILE_BYTES)    // after 2 A buffers
#define DYN_BYTES (6 * TILE_BYTES + 1024)

__device__ __forceinline__ uint32_t swz(uint32_t o) { return o ^ ((o >> 3) & 0x70u); }

__device__ __forceinline__ uint32_t smem_u32(const void* p) {
    uint32_t a;
    asm("{ .reg .u64 t; cvta.to.shared.u64 t, %1; cvt.u32.u64 %0, t; }" : "=r"(a) : "l"(p));
    return a;
}

#define LDSM4(r0, r1, r2, r3, addr) \
    asm volatile("ldmatrix.sync.aligned.m8n8.x4.shared.b16 {%0,%1,%2,%3}, [%4];" \
                 : "=r"(r0), "=r"(r1), "=r"(r2), "=r"(r3) : "r"(addr))
#define MMA16816(c, a, b0, b1) \
    asm volatile("mma.sync.aligned.m16n8k16.row.col.f32.f16.f16.f32 " \
                 "{%0,%1,%2,%3}, {%4,%5,%6,%7}, {%8,%9}, {%0,%1,%2,%3};" \
                 : "+f"((c)[0]), "+f"((c)[1]), "+f"((c)[2]), "+f"((c)[3]) \
                 : "r"((a)[0]), "r"((a)[1]), "r"((a)[2]), "r"((a)[3]), "r"(b0), "r"(b1))

// prefetch one A (x) chunk: 8 float4 per thread
__device__ __forceinline__ void a_load(const float* __restrict__ x, int bm, int u,
                                       int wid, int lane, float4* xr) {
#pragma unroll
    for (int it = 0; it < 4; it++) {
        const int row = wid * 4 + (lane >> 3) + 32 * it;
        const float* p = x + (size_t)(bm + row) * KDIM + u * 64 + (lane & 7) * 4;
        xr[it * 2 + 0] = *reinterpret_cast<const float4*>(p);
        xr[it * 2 + 1] = *reinterpret_cast<const float4*>(p + 32);
    }
}

// convert + store one A chunk into a swizzled fp16 tile
__device__ __forceinline__ void a_store(char* sb, int buf, const float4* xr,
                                        int wid, int lane) {
    char* base = sb + buf * TILE_BYTES;
#pragma unroll
    for (int it = 0; it < 4; it++) {
        const int row = wid * 4 + (lane >> 3) + 32 * it;
#pragma unroll
        for (int h = 0; h < 2; h++) {
            const float4 v = xr[it * 2 + h];
            __half2 p01 = __floats2half2_rn(v.x, v.y);
            __half2 p23 = __floats2half2_rn(v.z, v.w);
            const int col = (lane & 7) * 4 + 32 * h;
            const uint32_t off = swz((uint32_t)(row * 128 + col * 2));
            uint2 st;
            st.x = *reinterpret_cast<uint32_t*>(&p01);
            st.y = *reinterpret_cast<uint32_t*>(&p23);
            *reinterpret_cast<uint2*>(base + off) = st;
        }
    }
}

__global__ __launch_bounds__(256, 1)
void skan_mma_kernel(const float* __restrict__ x,
                     const float* __restrict__ w,
                     float* __restrict__ out)
{
    extern __shared__ char dynraw[];
    __shared__ float bias_s[BN];

    char* sb = (char*)(((uintptr_t)dynraw + 1023) & ~(uintptr_t)1023);
    const uint32_t sb_u = smem_u32(sb);

    const int tid = threadIdx.x;
    const int lane = tid & 31;
    const int wid = tid >> 5;
    const int bm = blockIdx.y * BM;
    const int bn = blockIdx.x * BN;
    const int wm = wid & 1;     // warp row (2 x 64)
    const int wn = wid >> 1;    // warp col (4 x 32)

    if (tid < BN)
        bias_s[tid] = fmaxf(__ldg(w + (size_t)(bn + tid) * WSTRIDE + 256), 0.0f);

    // ---- B fill (once): w[bn..bn+127][0..255] -> 4 resident fp16 chunk tiles ----
#pragma unroll 2
    for (int j = 0; j < 16; j++) {
        const int row = wid + 8 * j;
        const float* wr = w + (size_t)(bn + row) * WSTRIDE;
#pragma unroll
        for (int h = 0; h < 8; h++) {
            const int col = lane + 32 * h;                    // coalesced across lanes
            const __half v = __float2half_rn(__ldg(wr + col));
            char* dst = sb + B_OFF + (col >> 6) * TILE_BYTES +
                        swz((uint32_t)(row * 128 + (col & 63) * 2));
            *reinterpret_cast<__half*>(dst) = v;
        }
    }

    // ---- A chunk 0 ----
    float4 xr[8];
    a_load(x, bm, 0, wid, lane, xr);
    a_store(sb, 0, xr, wid, lane);
    __syncthreads();

    float acc[4][4][4];
#pragma unroll
    for (int mt = 0; mt < 4; mt++)
#pragma unroll
        for (int nt = 0; nt < 4; nt++)
#pragma unroll
            for (int q = 0; q < 4; q++) acc[mt][nt][q] = 0.0f;

    int buf = 0;
#pragma unroll 1
    for (int u = 0; u < 4; u++) {
        if (u < 3) a_load(x, bm, u + 1, wid, lane, xr);

        const uint32_t Abase = sb_u + buf * TILE_BYTES;
        const uint32_t Bbase = sb_u + B_OFF + u * TILE_BYTES;

#pragma unroll
        for (int kk = 0; kk < 4; kk++) {
            uint32_t A[4][4], Aa[4][4];
#pragma unroll
            for (int mt = 0; mt < 4; mt++) {
                const int row = wm * 64 + mt * 16 + (lane & 15);
                const int col = kk * 16 + (lane >> 4) * 8;
                const uint32_t addr = Abase + swz((uint32_t)(row * 128 + col * 2));
                LDSM4(A[mt][0], A[mt][1], A[mt][2], A[mt][3], addr);
            }
            // B: non-trans ldmatrix, A-style addressing on [n][k] tile.
            // matrices: 0 = n0:8 k-lo, 1 = n8:16 k-lo, 2 = n0:8 k-hi, 3 = n8:16 k-hi
            uint32_t B2[2][4], Ba[2][4];
#pragma unroll
            for (int np = 0; np < 2; np++) {
                const int nrow = wn * 32 + np * 16 + (lane & 15);
                const int ncol = kk * 16 + (lane >> 4) * 8;
                const uint32_t addr = Bbase + swz((uint32_t)(nrow * 128 + ncol * 2));
                LDSM4(B2[np][0], B2[np][1], B2[np][2], B2[np][3], addr);
            }
#pragma unroll
            for (int mt = 0; mt < 4; mt++)
#pragma unroll
                for (int q = 0; q < 4; q++) Aa[mt][q] = A[mt][q] & 0x7FFF7FFFu;
#pragma unroll
            for (int np = 0; np < 2; np++)
#pragma unroll
                for (int q = 0; q < 4; q++) Ba[np][q] = B2[np][q] & 0x7FFF7FFFu;

#pragma unroll
            for (int mt = 0; mt < 4; mt++)
#pragma unroll
                for (int nt = 0; nt < 4; nt++) {
                    const int np = nt >> 1, o = nt & 1;   // o: n8-group within 16
                    MMA16816(acc[mt][nt], A[mt],  B2[np][o], B2[np][o + 2]);
                    MMA16816(acc[mt][nt], Aa[mt], Ba[np][o], Ba[np][o + 2]);
                }
        }

        if (u < 3) {
            __syncthreads();
            a_store(sb, buf ^ 1, xr, wid, lane);
            __syncthreads();
            buf ^= 1;
        }
    }

    // ---- epilogue: y = 0.5*acc + relu(bias) ----
#pragma unroll
    for (int mt = 0; mt < 4; mt++) {
#pragma unroll
        for (int nt = 0; nt < 4; nt++) {
            const int r0 = bm + wm * 64 + mt * 16 + (lane >> 2);
            const int cl = wn * 32 + nt * 8 + (lane & 3) * 2;
            const float b0 = bias_s[cl], b1 = bias_s[cl + 1];
            float2 v0, v1;
            v0.x = 0.5f * acc[mt][nt][0] + b0;
            v0.y = 0.5f * acc[mt][nt][1] + b1;
            v1.x = 0.5f * acc[mt][nt][2] + b0;
            v1.y = 0.5f * acc[mt][nt][3] + b1;
            *reinterpret_cast<float2*>(out + (size_t)r0 * NDIM + bn + cl) = v0;
            *reinterpret_cast<float2*>(out + (size_t)(r0 + 8) * NDIM + bn + cl) = v1;
        }
    }
}

extern "C" void kernel_launch(void* const* d_in, const int* in_sizes, int n_in,
                              void* d_out, int out_size)
{
    const float* x = (const float*)d_in[0];   // (8192, 256)
    const float* w = (const float*)d_in[1];   // (256, 257)
    float* out = (float*)d_out;               // (8192, 256)

    cudaFuncSetAttribute(skan_mma_kernel,
                         cudaFuncAttributeMaxDynamicSharedMemorySize, DYN_BYTES);

    dim3 grid(NDIM / BN, 8192 / BM);          // (2, 64) = 128 CTAs, one wave
    dim3 block(256);
    skan_mma_kernel<<<grid, block, DYN_BYTES>>>(x, w, out);
}